// round 2
// baseline (speedup 1.0000x reference)
#include <cuda_runtime.h>
#include <math.h>

#define B    64
#define C    768
#define HW   576
#define NM   50
#define NSEL (B*NM)   // 3200
#define EPSV 1e-5f

typedef unsigned long long ull;

// ---------------- scratch (static device memory; no allocations) ----------------
__device__ float  g_G[(size_t)B*HW*HW];        // 84.9 MB Gram for cdist
__device__ float  g_a2[B*HW], g_b2[B*HW];      // squared norms
__device__ float  g_d2[2][B*HW];               // min d2 per input point
__device__ int    g_nn[2][B*HW];               // argmin index
__device__ int    g_sel_in[2][NSEL];           // selected input row idx
__device__ int    g_sel_c [2][NSEL];           // matched candidate row idx
__device__ float  g_X[4][(size_t)NSEL*C];      // gathered maps (n,c) row-major
__device__ float  g_S[6][(size_t)C*C];         // Grams X^T X (upper tiles valid)
__device__ float  g_csp[6][16][C];             // colsum partials
__device__ float  g_colsum[6][C];
__device__ double g_acc[32];

// ---------------- helpers ----------------
__device__ __forceinline__ void ffma2(ull &d, ull a, ull b) {
    asm("fma.rn.f32x2 %0, %1, %2, %0;" : "+l"(d) : "l"(a), "l"(b));
}

__device__ __forceinline__ float blockReduceSum(float v) {
    __shared__ float sw[32];
    int lane = threadIdx.x & 31, w = threadIdx.x >> 5;
    #pragma unroll
    for (int o = 16; o; o >>= 1) v += __shfl_xor_sync(~0u, v, o);
    if (lane == 0) sw[w] = v;
    __syncthreads();
    int nw = (blockDim.x + 31) >> 5;
    v = (threadIdx.x < nw) ? sw[threadIdx.x] : 0.f;
    if (w == 0) {
        #pragma unroll
        for (int o = 16; o; o >>= 1) v += __shfl_xor_sync(~0u, v, o);
    }
    return v; // valid in thread 0
}

// ---------------- kernels ----------------
__global__ void k_init() { if (threadIdx.x < 32) g_acc[threadIdx.x] = 0.0; }

// squared norms of map rows: maps[b,p,:] = spatial[b,:,p]
__global__ void k_norms(const float* __restrict__ s1, const float* __restrict__ s2) {
    int b = blockIdx.x, p = threadIdx.x;
    const float* src = blockIdx.y ? s2 : s1;
    float*       dst = blockIdx.y ? g_b2 : g_a2;
    const float* base = src + (size_t)b * C * HW + p;
    float s = 0.f;
    #pragma unroll 8
    for (int c = 0; c < C; c++) { float v = base[(size_t)c * HW]; s += v * v; }
    dst[b * HW + p] = s;
}

// G[b][m][n] = sum_c S1[b][c][m] * S2[b][c][n]   (K-major operands, coalesced)
// Inner loop uses packed fma.rn.f32x2; A tile stored DUPLICATED in smem so no MOVs.
__global__ void __launch_bounds__(256) k_gemm(const float* __restrict__ s1,
                                              const float* __restrict__ s2) {
    int b  = blockIdx.z;
    int m0 = blockIdx.y * 64, n0 = blockIdx.x * 64;
    const float* A  = s1 + (size_t)b * C * HW;
    const float* Bp = s2 + (size_t)b * C * HW;
    __shared__ float Asd[16][128];   // duplicated: Asd[k][2m..2m+1] = A[k][m]
    __shared__ float Bs [16][64];
    int tid = threadIdx.x;
    int tx = tid & 15, ty = tid >> 4;
    int lk = tid >> 4, lo = (tid & 15) * 4;
    ull acc[4][2] = {};
    for (int k0 = 0; k0 < C; k0 += 16) {
        float4 av = *(const float4*)&A [(size_t)(k0 + lk) * HW + m0 + lo];
        float4 bv = *(const float4*)&Bp[(size_t)(k0 + lk) * HW + n0 + lo];
        *(float4*)&Asd[lk][2*lo]     = make_float4(av.x, av.x, av.y, av.y);
        *(float4*)&Asd[lk][2*lo + 4] = make_float4(av.z, av.z, av.w, av.w);
        *(float4*)&Bs[lk][lo] = bv;
        __syncthreads();
        #pragma unroll
        for (int kk = 0; kk < 16; kk++) {
            float4 a01 = *(float4*)&Asd[kk][ty * 8];
            float4 a23 = *(float4*)&Asd[kk][ty * 8 + 4];
            float4 bb  = *(float4*)&Bs [kk][tx * 4];
            ull ad[4];
            ad[0] = ((ull*)&a01)[0]; ad[1] = ((ull*)&a01)[1];
            ad[2] = ((ull*)&a23)[0]; ad[3] = ((ull*)&a23)[1];
            ull b2lo = ((ull*)&bb)[0], b2hi = ((ull*)&bb)[1];
            #pragma unroll
            for (int i = 0; i < 4; i++) {
                ffma2(acc[i][0], ad[i], b2lo);
                ffma2(acc[i][1], ad[i], b2hi);
            }
        }
        __syncthreads();
    }
    float* Gout = g_G + (size_t)b * HW * HW;
    #pragma unroll
    for (int i = 0; i < 4; i++) {
        int m = m0 + ty * 4 + i;
        float4 o;
        ((ull*)&o)[0] = acc[i][0];
        ((ull*)&o)[1] = acc[i][1];
        *(float4*)&Gout[(size_t)m * HW + n0 + tx * 4] = o;
    }
}

// dir 1: per row m, argmin_n (b2[n]-2G[m,n]); warp per row
__global__ void k_rowmin() {
    int gwarp = (blockIdx.x * blockDim.x + threadIdx.x) >> 5;
    int lane  = threadIdx.x & 31;
    int b = gwarp / HW, m = gwarp % HW;
    const float* Grow = g_G + ((size_t)b * HW + m) * HW;
    const float* b2   = g_b2 + b * HW;
    float best = INFINITY; int bi = 0;
    for (int n = lane; n < HW; n += 32) {
        float v = b2[n] - 2.f * Grow[n];
        if (v < best || (v == best && n < bi)) { best = v; bi = n; }
    }
    #pragma unroll
    for (int o = 16; o; o >>= 1) {
        float ov = __shfl_xor_sync(~0u, best, o);
        int   oi = __shfl_xor_sync(~0u, bi, o);
        if (ov < best || (ov == best && oi < bi)) { best = ov; bi = oi; }
    }
    if (lane == 0) {
        float d2 = g_a2[b * HW + m] + best;
        g_d2[0][b * HW + m] = d2 > 0.f ? d2 : 0.f;
        g_nn[0][b * HW + m] = bi;
    }
}

// dir 2: per column n, argmin_m (a2[m]-2G[m,n]); thread per column (coalesced)
__global__ void k_colmin() {
    int b = blockIdx.x, n = threadIdx.x;
    const float* Gb = g_G + (size_t)b * HW * HW;
    const float* a2 = g_a2 + b * HW;
    float best = INFINITY; int bi = 0;
    #pragma unroll 4
    for (int m = 0; m < HW; m++) {
        float v = a2[m] - 2.f * Gb[(size_t)m * HW + n];
        if (v < best) { best = v; bi = m; }   // strict < -> lowest index on ties
    }
    float d2 = g_b2[b * HW + n] + best;
    g_d2[1][b * HW + n] = d2 > 0.f ? d2 : 0.f;
    g_nn[1][b * HW + n] = bi;
}

// rank-based top-50 smallest (ties -> lowest index), matches jax top_k semantics
__global__ void k_select() {
    int b = blockIdx.x, dir = blockIdx.y;
    __shared__ float sd[HW];
    int i = threadIdx.x;
    sd[i] = g_d2[dir][b * HW + i];
    __syncthreads();
    float di = sd[i];
    int rank = 0;
    for (int j = 0; j < HW; j++) {
        float dj = sd[j];
        rank += (dj < di) || (dj == di && j < i);
    }
    if (rank < NM) {
        g_sel_in[dir][b * NM + rank] = i;
        g_sel_c [dir][b * NM + rank] = g_nn[dir][b * HW + i];
    }
}

// gather selected rows into (n,c) row-major scratch + accumulate invariance sums
__global__ void k_gather(const float* __restrict__ s1, const float* __restrict__ s2) {
    int k = blockIdx.x, b = blockIdx.y, dir = blockIdx.z;
    const float* srcin = dir ? s2 : s1;
    const float* srcc  = dir ? s1 : s2;
    int pin = g_sel_in[dir][b * NM + k];
    int pc  = g_sel_c [dir][b * NM + k];
    float* Xin = g_X[dir * 2 + 0];
    float* Xc  = g_X[dir * 2 + 1];
    int row = b * NM + k;
    float lsum = 0.f;
    for (int c = threadIdx.x; c < C; c += 256) {
        float vi = srcin[((size_t)b * C + c) * HW + pin];
        float vc = srcc [((size_t)b * C + c) * HW + pc];
        Xin[(size_t)row * C + c] = vi;
        Xc [(size_t)row * C + c] = vc;
        float d = vi - vc; lsum += d * d;
    }
    float tot = blockReduceSum(lsum);
    if (threadIdx.x == 0) atomicAdd(&g_acc[1 + dir], (double)tot);
}

__global__ void k_pooled_inv(const float* __restrict__ p1, const float* __restrict__ p2) {
    float lsum = 0.f;
    for (int i = blockIdx.x * blockDim.x + threadIdx.x; i < B * C; i += gridDim.x * blockDim.x) {
        float d = p1[i] - p2[i]; lsum += d * d;
    }
    float tot = blockReduceSum(lsum);
    if (threadIdx.x == 0) atomicAdd(&g_acc[0], (double)tot);
}

__device__ __forceinline__ const float* tensor_ptr(int t, const float* p1, const float* p2) {
    if (t < 4) return g_X[t];
    return (t == 4) ? p1 : p2;
}
__device__ __forceinline__ int tensor_n(int t) { return (t < 4) ? NSEL : B; }

// column sums (partials, deterministic 2-stage)
__global__ void k_colsum_part(const float* __restrict__ p1, const float* __restrict__ p2) {
    int t = blockIdx.x, chunk = blockIdx.y, c = threadIdx.x;
    const float* X = tensor_ptr(t, p1, p2);
    int n = tensor_n(t);
    int step = n / 16;
    int n0 = chunk * step, n1 = n0 + step;
    float s = 0.f;
    for (int i = n0; i < n1; i++) s += X[(size_t)i * C + c];
    g_csp[t][chunk][c] = s;
}
__global__ void k_colsum_fin() {
    int t = blockIdx.x, c = threadIdx.x;
    float s = 0.f;
    #pragma unroll
    for (int k = 0; k < 16; k++) s += g_csp[t][k][c];
    g_colsum[t][c] = s;
}

// S = X^T X, upper-triangle 64x64 tiles only (78 tiles of 12x12); f32x2 inner loop
__global__ void __launch_bounds__(256) k_gram(const float* __restrict__ p1,
                                              const float* __restrict__ p2) {
    int t = blockIdx.y;
    const float* X = tensor_ptr(t, p1, p2);
    int n = tensor_n(t);
    // linear tile -> (i,j), i<=j among 12x12
    int idx = blockIdx.x, ti = 0;
    while (idx >= 12 - ti) { idx -= 12 - ti; ti++; }
    int tj = ti + idx;
    int i0 = ti * 64, j0 = tj * 64;

    __shared__ float Asd[16][128];
    __shared__ float Bs [16][64];
    int tid = threadIdx.x;
    int tx = tid & 15, ty = tid >> 4;
    int lk = tid >> 4, lo = (tid & 15) * 4;
    ull acc[4][2] = {};
    for (int k0 = 0; k0 < n; k0 += 16) {
        float4 av = *(const float4*)&X[(size_t)(k0 + lk) * C + i0 + lo];
        float4 bv = *(const float4*)&X[(size_t)(k0 + lk) * C + j0 + lo];
        *(float4*)&Asd[lk][2*lo]     = make_float4(av.x, av.x, av.y, av.y);
        *(float4*)&Asd[lk][2*lo + 4] = make_float4(av.z, av.z, av.w, av.w);
        *(float4*)&Bs[lk][lo] = bv;
        __syncthreads();
        #pragma unroll
        for (int kk = 0; kk < 16; kk++) {
            float4 a01 = *(float4*)&Asd[kk][ty * 8];
            float4 a23 = *(float4*)&Asd[kk][ty * 8 + 4];
            float4 bb  = *(float4*)&Bs [kk][tx * 4];
            ull ad[4];
            ad[0] = ((ull*)&a01)[0]; ad[1] = ((ull*)&a01)[1];
            ad[2] = ((ull*)&a23)[0]; ad[3] = ((ull*)&a23)[1];
            ull b2lo = ((ull*)&bb)[0], b2hi = ((ull*)&bb)[1];
            #pragma unroll
            for (int i = 0; i < 4; i++) {
                ffma2(acc[i][0], ad[i], b2lo);
                ffma2(acc[i][1], ad[i], b2hi);
            }
        }
        __syncthreads();
    }
    float* Sp = g_S[t];
    #pragma unroll
    for (int i = 0; i < 4; i++) {
        int c1 = i0 + ty * 4 + i;
        float4 o;
        ((ull*)&o)[0] = acc[i][0];
        ((ull*)&o)[1] = acc[i][1];
        *(float4*)&Sp[(size_t)c1 * C + j0 + tx * 4] = o;
    }
}

// std term per tensor: sum_c relu(1 - sqrt(var_c + eps)), var from Gram diag + colsum
__global__ void k_std() {
    int t = blockIdx.x, c = threadIdx.x;
    float n  = (float)tensor_n(t);
    float mu = g_colsum[t][c] / n;
    float Scc = g_S[t][(size_t)c * C + c];
    float var = (Scc - n * mu * mu) / (n - 1.f);
    float sd  = sqrtf(var + EPSV);
    float contrib = fmaxf(1.f - sd, 0.f);
    float tot = blockReduceSum(contrib);
    if (threadIdx.x == 0) atomicAdd(&g_acc[3 + t], (double)tot);
}

// off-diagonal squared sum of cov = (S - n mu mu^T)/(n-1), upper tiles, x2 weight
__global__ void k_cov() {
    int t = blockIdx.y;
    float n = (float)tensor_n(t);
    float inv_nm1 = 1.f / (n - 1.f);
    int idx = blockIdx.x, ti = 0;
    while (idx >= 12 - ti) { idx -= 12 - ti; ti++; }
    int tj = ti + idx;
    int i0 = ti * 64, j0 = tj * 64;
    const float* Sp = g_S[t];
    float lsum = 0.f;
    #pragma unroll
    for (int it = 0; it < 16; it++) {
        int e = it * 256 + threadIdx.x;
        int r = e >> 6, cc = e & 63;
        int c1 = i0 + r, c2 = j0 + cc;
        if (c2 > c1) {
            float mu1 = g_colsum[t][c1] / n;
            float mu2 = g_colsum[t][c2] / n;
            float cov = (Sp[(size_t)c1 * C + c2] - n * mu1 * mu2) * inv_nm1;
            lsum += 2.f * cov * cov;
        }
    }
    float tot = blockReduceSum(lsum);
    if (threadIdx.x == 0) atomicAdd(&g_acc[10 + t], (double)tot);
}

__global__ void k_final(float* __restrict__ out) {
    double inv_g = g_acc[0] / (double)(B * C);
    double inv1  = g_acc[1] / (double)((size_t)NSEL * C);
    double inv2  = g_acc[2] / (double)((size_t)NSEL * C);
    double stdt[6], covt[6];
    for (int t = 0; t < 6; t++) {
        stdt[t] = (g_acc[3 + t] / (double)C) * 0.5;   // mean(relu)/2
        covt[t] = g_acc[10 + t] / (double)C;          // off_diag_sq_sum / C
    }
    double glob = 25.0 * inv_g + 25.0 * (stdt[4] + stdt[5]) + (covt[4] + covt[5]);
    double loc  = 0.5 * (25.0 * inv1 + 25.0 * inv2)
                + 0.5 * (25.0 * (stdt[0] + stdt[1]) + 25.0 * (stdt[2] + stdt[3]))
                + 0.5 * ((covt[0] + covt[1]) + (covt[2] + covt[3]));
    out[0] = (float)(0.5 * glob + 0.5 * loc);
}

// ---------------- launch ----------------
extern "C" void kernel_launch(void* const* d_in, const int* in_sizes, int n_in,
                              void* d_out, int out_size) {
    const float* s1 = (const float*)d_in[0];
    const float* p1 = (const float*)d_in[1];
    const float* s2 = (const float*)d_in[2];
    const float* p2 = (const float*)d_in[3];
    float* out = (float*)d_out;

    k_init<<<1, 32>>>();
    k_norms<<<dim3(B, 2), HW>>>(s1, s2);
    k_gemm<<<dim3(9, 9, B), 256>>>(s1, s2);
    k_rowmin<<<(B * HW) / 8, 256>>>();
    k_colmin<<<B, HW>>>();
    k_select<<<dim3(B, 2), HW>>>();
    k_gather<<<dim3(NM, B, 2), 256>>>(s1, s2);
    k_pooled_inv<<<48, 256>>>(p1, p2);
    k_colsum_part<<<dim3(6, 16), C>>>(p1, p2);
    k_colsum_fin<<<6, C>>>();
    k_gram<<<dim3(78, 6), 256>>>(p1, p2);
    k_std<<<6, C>>>();
    k_cov<<<dim3(78, 6), 256>>>();
    k_final<<<1, 1>>>(out);
}

// round 4
// speedup vs baseline: 1.8920x; 1.8920x over previous
#include <cuda_runtime.h>
#include <cstdint>
#include <math.h>

#define B    64
#define C    768
#define HW   576
#define NM   50
#define NSEL (B*NM)   // 3200
#define EPSV 1e-5f
#define KC   32

// ---------------- scratch (static device memory; no allocations) ----------------
__device__ float  g_G[(size_t)B*HW*HW];        // 84.9 MB Gram for cdist
__device__ float  g_a2[B*HW], g_b2[B*HW];      // squared norms
__device__ float  g_d2[2][B*HW];               // min d2 per input point
__device__ int    g_nn[2][B*HW];               // argmin index
__device__ int    g_sel_in[2][NSEL];           // selected input row idx
__device__ int    g_sel_c [2][NSEL];           // matched candidate row idx
__device__ float  g_X[4][(size_t)NSEL*C];      // gathered maps (n,c) row-major
__device__ float  g_S[6][(size_t)C*C];         // Grams X^T X (upper tiles valid)
__device__ float  g_csp[6][16][C];             // colsum partials
__device__ float  g_colsum[6][C];
__device__ double g_acc[32];

// ---------------- helpers ----------------
__device__ __forceinline__ uint32_t f2tf32(float f) {
    uint32_t r;
    asm("cvt.rna.tf32.f32 %0, %1;" : "=r"(r) : "f"(f));
    return r;
}
__device__ __forceinline__ void mma_tf32(float c[4], const uint32_t a[4], const uint32_t b[2]) {
    asm volatile(
        "mma.sync.aligned.m16n8k8.row.col.f32.tf32.tf32.f32 "
        "{%0,%1,%2,%3}, {%4,%5,%6,%7}, {%8,%9}, {%0,%1,%2,%3};"
        : "+f"(c[0]), "+f"(c[1]), "+f"(c[2]), "+f"(c[3])
        : "r"(a[0]), "r"(a[1]), "r"(a[2]), "r"(a[3]), "r"(b[0]), "r"(b[1]));
}

__device__ __forceinline__ float blockReduceSum(float v) {
    __shared__ float sw[32];
    int lane = threadIdx.x & 31, w = threadIdx.x >> 5;
    #pragma unroll
    for (int o = 16; o; o >>= 1) v += __shfl_xor_sync(~0u, v, o);
    if (lane == 0) sw[w] = v;
    __syncthreads();
    int nw = (blockDim.x + 31) >> 5;
    v = (threadIdx.x < nw) ? sw[threadIdx.x] : 0.f;
    if (w == 0) {
        #pragma unroll
        for (int o = 16; o; o >>= 1) v += __shfl_xor_sync(~0u, v, o);
    }
    return v;
}

// ---------------- kernels ----------------
__global__ void k_init() { if (threadIdx.x < 32) g_acc[threadIdx.x] = 0.0; }

__global__ void k_norms(const float* __restrict__ s1, const float* __restrict__ s2) {
    int b = blockIdx.x, p = threadIdx.x;
    const float* src = blockIdx.y ? s2 : s1;
    float*       dst = blockIdx.y ? g_b2 : g_a2;
    const float* base = src + (size_t)b * C * HW + p;
    float s = 0.f;
    #pragma unroll 8
    for (int c = 0; c < C; c++) { float v = base[(size_t)c * HW]; s += v * v; }
    dst[b * HW + p] = s;
}

// ---- tf32 HMMA GEMM: G[b] = maps1[b] @ maps2[b]^T  (K-major operands) ----
// CTA tile 128x128, 8 warps (2m x 4n), warp tile 64x32, KC=32.
__global__ void __launch_bounds__(256, 2) k_gemm_mma(const float* __restrict__ s1,
                                                     const float* __restrict__ s2) {
    __shared__ uint32_t As[KC][132];   // As[k][m], padded: bank = (4k+m)%32
    __shared__ uint32_t Bs[KC][132];

    int b  = blockIdx.z;
    int m0 = blockIdx.y * 128, n0 = blockIdx.x * 128;
    int tid = threadIdx.x, w = tid >> 5, lane = tid & 31;
    int wm = (w & 1) * 64, wn = (w >> 1) * 32;
    int gr = lane >> 2, gc = lane & 3;    // groupID, thread-in-group

    const float* Ag = s1 + (size_t)b * C * HW;
    const float* Bg = s2 + (size_t)b * C * HW;

    float acc[4][4][4] = {};   // [mfrag][nfrag][reg]

    int ldrow4 = tid >> 5;          // 0..7
    int ldcol  = (tid & 31) * 4;    // float4 col
    int gmA = m0 + ldcol; if (gmA > HW - 4) gmA = HW - 4;
    int gmB = n0 + ldcol; if (gmB > HW - 4) gmB = HW - 4;

    for (int k0 = 0; k0 < C; k0 += KC) {
        __syncthreads();
        #pragma unroll
        for (int r = 0; r < 4; r++) {
            int krow = ldrow4 + r * 8;
            float4 va = *(const float4*)&Ag[(size_t)(k0 + krow) * HW + gmA];
            float4 vb = *(const float4*)&Bg[(size_t)(k0 + krow) * HW + gmB];
            uint32_t* pa = &As[krow][ldcol];
            uint32_t* pb = &Bs[krow][ldcol];
            pa[0] = f2tf32(va.x); pa[1] = f2tf32(va.y); pa[2] = f2tf32(va.z); pa[3] = f2tf32(va.w);
            pb[0] = f2tf32(vb.x); pb[1] = f2tf32(vb.y); pb[2] = f2tf32(vb.z); pb[3] = f2tf32(vb.w);
        }
        __syncthreads();
        #pragma unroll
        for (int ks = 0; ks < KC; ks += 8) {
            uint32_t af[4][4], bf[4][2];
            #pragma unroll
            for (int i = 0; i < 4; i++) {
                int mb = wm + i * 16;
                af[i][0] = As[ks + gc    ][mb + gr    ];
                af[i][1] = As[ks + gc    ][mb + gr + 8];
                af[i][2] = As[ks + gc + 4][mb + gr    ];
                af[i][3] = As[ks + gc + 4][mb + gr + 8];
            }
            #pragma unroll
            for (int j = 0; j < 4; j++) {
                int nb = wn + j * 8;
                bf[j][0] = Bs[ks + gc    ][nb + gr];
                bf[j][1] = Bs[ks + gc + 4][nb + gr];
            }
            #pragma unroll
            for (int i = 0; i < 4; i++)
                #pragma unroll
                for (int j = 0; j < 4; j++)
                    mma_tf32(acc[i][j], af[i], bf[j]);
        }
    }

    // epilogue: c0,c1 -> (m, n..n+1); c2,c3 -> (m+8, n..n+1)
    float* Gb = g_G + (size_t)b * HW * HW;
    #pragma unroll
    for (int i = 0; i < 4; i++) {
        int m = m0 + wm + i * 16 + gr;
        #pragma unroll
        for (int j = 0; j < 4; j++) {
            int n = n0 + wn + j * 8 + gc * 2;
            if (n < HW) {
                if (m < HW)
                    *(float2*)&Gb[(size_t)m * HW + n] = make_float2(acc[i][j][0], acc[i][j][1]);
                if (m + 8 < HW)
                    *(float2*)&Gb[(size_t)(m + 8) * HW + n] = make_float2(acc[i][j][2], acc[i][j][3]);
            }
        }
    }
}

// dir 1: per row m, argmin_n (b2[n]-2G[m,n]); warp per row
__global__ void k_rowmin() {
    int gwarp = (blockIdx.x * blockDim.x + threadIdx.x) >> 5;
    int lane  = threadIdx.x & 31;
    int b = gwarp / HW, m = gwarp % HW;
    const float* Grow = g_G + ((size_t)b * HW + m) * HW;
    const float* b2   = g_b2 + b * HW;
    float best = INFINITY; int bi = 0;
    for (int n = lane; n < HW; n += 32) {
        float v = b2[n] - 2.f * Grow[n];
        if (v < best || (v == best && n < bi)) { best = v; bi = n; }
    }
    #pragma unroll
    for (int o = 16; o; o >>= 1) {
        float ov = __shfl_xor_sync(~0u, best, o);
        int   oi = __shfl_xor_sync(~0u, bi, o);
        if (ov < best || (ov == best && oi < bi)) { best = ov; bi = oi; }
    }
    if (lane == 0) {
        float d2 = g_a2[b * HW + m] + best;
        g_d2[0][b * HW + m] = d2 > 0.f ? d2 : 0.f;
        g_nn[0][b * HW + m] = bi;
    }
}

// dir 2: per column n, argmin_m (a2[m]-2G[m,n]); thread per column (coalesced)
__global__ void k_colmin() {
    int b = blockIdx.x, n = threadIdx.x;
    const float* Gb = g_G + (size_t)b * HW * HW;
    const float* a2 = g_a2 + b * HW;
    float best = INFINITY; int bi = 0;
    #pragma unroll 4
    for (int m = 0; m < HW; m++) {
        float v = a2[m] - 2.f * Gb[(size_t)m * HW + n];
        if (v < best) { best = v; bi = m; }
    }
    float d2 = g_b2[b * HW + n] + best;
    g_d2[1][b * HW + n] = d2 > 0.f ? d2 : 0.f;
    g_nn[1][b * HW + n] = bi;
}

// rank-based top-50 smallest (ties -> lowest index)
__global__ void k_select() {
    int b = blockIdx.x, dir = blockIdx.y;
    __shared__ float sd[HW];
    int i = threadIdx.x;
    sd[i] = g_d2[dir][b * HW + i];
    __syncthreads();
    float di = sd[i];
    int rank = 0;
    for (int j = 0; j < HW; j++) {
        float dj = sd[j];
        rank += (dj < di) || (dj == di && j < i);
    }
    if (rank < NM) {
        g_sel_in[dir][b * NM + rank] = i;
        g_sel_c [dir][b * NM + rank] = g_nn[dir][b * HW + i];
    }
}

__global__ void k_gather(const float* __restrict__ s1, const float* __restrict__ s2) {
    int k = blockIdx.x, b = blockIdx.y, dir = blockIdx.z;
    const float* srcin = dir ? s2 : s1;
    const float* srcc  = dir ? s1 : s2;
    int pin = g_sel_in[dir][b * NM + k];
    int pc  = g_sel_c [dir][b * NM + k];
    float* Xin = g_X[dir * 2 + 0];
    float* Xc  = g_X[dir * 2 + 1];
    int row = b * NM + k;
    float lsum = 0.f;
    for (int c = threadIdx.x; c < C; c += 256) {
        float vi = srcin[((size_t)b * C + c) * HW + pin];
        float vc = srcc [((size_t)b * C + c) * HW + pc];
        Xin[(size_t)row * C + c] = vi;
        Xc [(size_t)row * C + c] = vc;
        float d = vi - vc; lsum += d * d;
    }
    float tot = blockReduceSum(lsum);
    if (threadIdx.x == 0) atomicAdd(&g_acc[1 + dir], (double)tot);
}

__global__ void k_pooled_inv(const float* __restrict__ p1, const float* __restrict__ p2) {
    float lsum = 0.f;
    for (int i = blockIdx.x * blockDim.x + threadIdx.x; i < B * C; i += gridDim.x * blockDim.x) {
        float d = p1[i] - p2[i]; lsum += d * d;
    }
    float tot = blockReduceSum(lsum);
    if (threadIdx.x == 0) atomicAdd(&g_acc[0], (double)tot);
}

__device__ __forceinline__ const float* tensor_ptr(int t, const float* p1, const float* p2) {
    if (t < 4) return g_X[t];
    return (t == 4) ? p1 : p2;
}
__device__ __forceinline__ int tensor_n(int t) { return (t < 4) ? NSEL : B; }

__global__ void k_colsum_part(const float* __restrict__ p1, const float* __restrict__ p2) {
    int t = blockIdx.x, chunk = blockIdx.y, c = threadIdx.x;
    const float* X = tensor_ptr(t, p1, p2);
    int n = tensor_n(t);
    int step = n / 16;
    int n0 = chunk * step, n1 = n0 + step;
    float s = 0.f;
    for (int i = n0; i < n1; i++) s += X[(size_t)i * C + c];
    g_csp[t][chunk][c] = s;
}
__global__ void k_colsum_fin() {
    int t = blockIdx.x, c = threadIdx.x;
    float s = 0.f;
    #pragma unroll
    for (int k = 0; k < 16; k++) s += g_csp[t][k][c];
    g_colsum[t][c] = s;
}

// S = X^T X, upper-triangle 64x64 tiles (78 of 12x12), exact fp32 scalar
__global__ void __launch_bounds__(256) k_gram(const float* __restrict__ p1,
                                              const float* __restrict__ p2) {
    int t = blockIdx.y;
    const float* X = tensor_ptr(t, p1, p2);
    int n = tensor_n(t);
    int idx = blockIdx.x, ti = 0;
    while (idx >= 12 - ti) { idx -= 12 - ti; ti++; }
    int tj = ti + idx;
    int i0 = ti * 64, j0 = tj * 64;

    __shared__ float As[16][64], Bs[16][64];
    int tid = threadIdx.x;
    int tx = tid & 15, ty = tid >> 4;
    int lk = tid >> 4, lo = (tid & 15) * 4;
    float acc[4][4] = {};
    for (int k0 = 0; k0 < n; k0 += 16) {
        *(float4*)&As[lk][lo] = *(const float4*)&X[(size_t)(k0 + lk) * C + i0 + lo];
        *(float4*)&Bs[lk][lo] = *(const float4*)&X[(size_t)(k0 + lk) * C + j0 + lo];
        __syncthreads();
        #pragma unroll
        for (int kk = 0; kk < 16; kk++) {
            float a[4], bb[4];
            *(float4*)a  = *(float4*)&As[kk][ty * 4];
            *(float4*)bb = *(float4*)&Bs[kk][tx * 4];
            #pragma unroll
            for (int i = 0; i < 4; i++)
                #pragma unroll
                for (int j = 0; j < 4; j++) acc[i][j] += a[i] * bb[j];
        }
        __syncthreads();
    }
    float* Sp = g_S[t];
    #pragma unroll
    for (int i = 0; i < 4; i++) {
        int c1 = i0 + ty * 4 + i;
        *(float4*)&Sp[(size_t)c1 * C + j0 + tx * 4] = *(float4*)acc[i];
    }
}

__global__ void k_std() {
    int t = blockIdx.x, c = threadIdx.x;
    float n  = (float)tensor_n(t);
    float mu = g_colsum[t][c] / n;
    float Scc = g_S[t][(size_t)c * C + c];
    float var = (Scc - n * mu * mu) / (n - 1.f);
    float sd  = sqrtf(var + EPSV);
    float contrib = fmaxf(1.f - sd, 0.f);
    float tot = blockReduceSum(contrib);
    if (threadIdx.x == 0) atomicAdd(&g_acc[3 + t], (double)tot);
}

__global__ void k_cov() {
    int t = blockIdx.y;
    float n = (float)tensor_n(t);
    float inv_nm1 = 1.f / (n - 1.f);
    int idx = blockIdx.x, ti = 0;
    while (idx >= 12 - ti) { idx -= 12 - ti; ti++; }
    int tj = ti + idx;
    int i0 = ti * 64, j0 = tj * 64;
    const float* Sp = g_S[t];
    float lsum = 0.f;
    #pragma unroll
    for (int it = 0; it < 16; it++) {
        int e = it * 256 + threadIdx.x;
        int r = e >> 6, cc = e & 63;
        int c1 = i0 + r, c2 = j0 + cc;
        if (c2 > c1) {
            float mu1 = g_colsum[t][c1] / n;
            float mu2 = g_colsum[t][c2] / n;
            float cov = (Sp[(size_t)c1 * C + c2] - n * mu1 * mu2) * inv_nm1;
            lsum += 2.f * cov * cov;
        }
    }
    float tot = blockReduceSum(lsum);
    if (threadIdx.x == 0) atomicAdd(&g_acc[10 + t], (double)tot);
}

__global__ void k_final(float* __restrict__ out) {
    double inv_g = g_acc[0] / (double)(B * C);
    double inv1  = g_acc[1] / (double)((size_t)NSEL * C);
    double inv2  = g_acc[2] / (double)((size_t)NSEL * C);
    double stdt[6], covt[6];
    for (int t = 0; t < 6; t++) {
        stdt[t] = (g_acc[3 + t] / (double)C) * 0.5;
        covt[t] = g_acc[10 + t] / (double)C;
    }
    double glob = 25.0 * inv_g + 25.0 * (stdt[4] + stdt[5]) + (covt[4] + covt[5]);
    double loc  = 0.5 * (25.0 * inv1 + 25.0 * inv2)
                + 0.5 * (25.0 * (stdt[0] + stdt[1]) + 25.0 * (stdt[2] + stdt[3]))
                + 0.5 * ((covt[0] + covt[1]) + (covt[2] + covt[3]));
    out[0] = (float)(0.5 * glob + 0.5 * loc);
}

// ---------------- launch ----------------
extern "C" void kernel_launch(void* const* d_in, const int* in_sizes, int n_in,
                              void* d_out, int out_size) {
    const float* s1 = (const float*)d_in[0];
    const float* p1 = (const float*)d_in[1];
    const float* s2 = (const float*)d_in[2];
    const float* p2 = (const float*)d_in[3];
    float* out = (float*)d_out;

    k_init<<<1, 32>>>();
    k_norms<<<dim3(B, 2), HW>>>(s1, s2);
    k_gemm_mma<<<dim3(5, 5, B), 256>>>(s1, s2);
    k_rowmin<<<(B * HW) / 8, 256>>>();
    k_colmin<<<B, HW>>>();
    k_select<<<dim3(B, 2), HW>>>();
    k_gather<<<dim3(NM, B, 2), 256>>>(s1, s2);
    k_pooled_inv<<<48, 256>>>(p1, p2);
    k_colsum_part<<<dim3(6, 16), C>>>(p1, p2);
    k_colsum_fin<<<6, C>>>();
    k_gram<<<dim3(78, 6), 256>>>(p1, p2);
    k_std<<<6, C>>>();
    k_cov<<<dim3(78, 6), 256>>>();
    k_final<<<1, 1>>>(out);
}

// round 5
// speedup vs baseline: 2.0892x; 1.1042x over previous
#include <cuda_runtime.h>
#include <cstdint>
#include <math.h>

#define B    64
#define C    768
#define HW   576
#define NM   50
#define NSEL (B*NM)   // 3200
#define EPSV 1e-5f
#define KC   32
#define NCH  (C/KC)   // 24

typedef unsigned long long ull;

// ---------------- scratch ----------------
__device__ float  g_a2[B*HW], g_b2[B*HW];      // squared norms
__device__ ull    g_key[2][B*HW];              // packed (enc(minval)<<32)|argmin
__device__ int    g_sel_in[2][NSEL];
__device__ int    g_sel_c [2][NSEL];
__device__ float  g_X[4][(size_t)NSEL*C];
__device__ float  g_S[6][(size_t)C*C];
__device__ float  g_csp[6][16][C];
__device__ float  g_colsum[6][C];
__device__ double g_acc[32];

// ---------------- helpers ----------------
__device__ __forceinline__ void mma_tf32(float c[4], const uint32_t a[4], const uint32_t b[2]) {
    asm volatile(
        "mma.sync.aligned.m16n8k8.row.col.f32.tf32.tf32.f32 "
        "{%0,%1,%2,%3}, {%4,%5,%6,%7}, {%8,%9}, {%0,%1,%2,%3};"
        : "+f"(c[0]), "+f"(c[1]), "+f"(c[2]), "+f"(c[3])
        : "r"(a[0]), "r"(a[1]), "r"(a[2]), "r"(a[3]), "r"(b[0]), "r"(b[1]));
}
#define CP_A16(d, s) asm volatile("cp.async.ca.shared.global [%0], [%1], 16;" :: "r"(d), "l"(s))
#define CP_COMMIT()  asm volatile("cp.async.commit_group;" ::: "memory")
#define CP_WAIT1()   asm volatile("cp.async.wait_group 1;" ::: "memory")
#define CP_WAIT0()   asm volatile("cp.async.wait_group 0;" ::: "memory")

__device__ __forceinline__ uint32_t smem_u32(const void* p) {
    uint32_t a;
    asm("{ .reg .u64 t; cvta.to.shared.u64 t, %1; cvt.u32.u64 %0, t; }" : "=r"(a) : "l"(p));
    return a;
}
// sortable encoding: min over keys == (min value, then min index)
__device__ __forceinline__ ull enc_key(float f, int idx) {
    uint32_t u = __float_as_uint(f);
    u = (u & 0x80000000u) ? ~u : (u | 0x80000000u);
    return ((ull)u << 32) | (uint32_t)idx;
}
__device__ __forceinline__ float dec_val(ull k) {
    uint32_t e = (uint32_t)(k >> 32);
    uint32_t u = (e & 0x80000000u) ? (e ^ 0x80000000u) : ~e;
    return __uint_as_float(u);
}

__device__ __forceinline__ float blockReduceSum(float v) {
    __shared__ float sw[32];
    int lane = threadIdx.x & 31, w = threadIdx.x >> 5;
    #pragma unroll
    for (int o = 16; o; o >>= 1) v += __shfl_xor_sync(~0u, v, o);
    if (lane == 0) sw[w] = v;
    __syncthreads();
    int nw = (blockDim.x + 31) >> 5;
    v = (threadIdx.x < nw) ? sw[threadIdx.x] : 0.f;
    if (w == 0) {
        #pragma unroll
        for (int o = 16; o; o >>= 1) v += __shfl_xor_sync(~0u, v, o);
    }
    return v;
}

// ---------------- kernels ----------------
__global__ void k_init() { if (threadIdx.x < 32) g_acc[threadIdx.x] = 0.0; }
__global__ void k_keyinit() {
    int i = blockIdx.x * blockDim.x + threadIdx.x;
    if (i < 2 * B * HW) ((ull*)g_key)[i] = ~0ull;
}

__global__ void k_norms(const float* __restrict__ s1, const float* __restrict__ s2) {
    int b = blockIdx.x, p = threadIdx.x;
    const float* src = blockIdx.y ? s2 : s1;
    float*       dst = blockIdx.y ? g_b2 : g_a2;
    const float* base = src + (size_t)b * C * HW + p;
    float s = 0.f;
    #pragma unroll 8
    for (int c = 0; c < C; c++) { float v = base[(size_t)c * HW]; s += v * v; }
    dst[b * HW + p] = s;
}

// ---- fused tf32 GEMM + row/col argmin. CTA 128x128, 8 warps (2m x 4n), cp.async x2 ----
#define SSTRIDE 8448          // u32 per stage (A 32*132 + B 32*132)
#define GSMEM   (2 * SSTRIDE * 4)

__global__ void __launch_bounds__(256, 2) k_gemm_fused(const float* __restrict__ s1,
                                                       const float* __restrict__ s2) {
    extern __shared__ uint32_t dyn[];
    int b  = blockIdx.z;
    int m0 = blockIdx.y * 128, n0 = blockIdx.x * 128;
    int tid = threadIdx.x, w = tid >> 5, lane = tid & 31;
    int wm = (w & 1) * 64, wn = (w >> 1) * 32;
    int gr = lane >> 2, gc = lane & 3;

    const float* Ag = s1 + (size_t)b * C * HW;
    const float* Bg = s2 + (size_t)b * C * HW;
    uint32_t sbase = smem_u32(dyn);

    // per-thread copy slots: 4 float4 per matrix per chunk
    int rowv[4], colA[4], colB[4];
    #pragma unroll
    for (int t = 0; t < 4; t++) {
        int v = tid + t * 256;
        rowv[t] = v >> 5;
        int col = (v & 31) * 4;
        int ca = m0 + col; if (ca > HW - 4) ca = HW - 4;
        int cb = n0 + col; if (cb > HW - 4) cb = HW - 4;
        colA[t] = ca; colB[t] = cb;
    }
    auto issue_chunk = [&](int s, int stage) {
        int k0 = s * KC;
        uint32_t sA = sbase + stage * (SSTRIDE * 4);
        uint32_t sB = sA + 4224 * 4;
        #pragma unroll
        for (int t = 0; t < 4; t++) {
            int v = tid + t * 256;
            uint32_t so = ((v >> 5) * 132 + (v & 31) * 4) * 4;
            CP_A16(sA + so, (const char*)&Ag[(size_t)(k0 + rowv[t]) * HW + colA[t]]);
            CP_A16(sB + so, (const char*)&Bg[(size_t)(k0 + rowv[t]) * HW + colB[t]]);
        }
        CP_COMMIT();
    };

    float acc[4][4][4] = {};
    issue_chunk(0, 0);
    for (int s = 0; s < NCH; s++) {
        if (s + 1 < NCH) { issue_chunk(s + 1, (s + 1) & 1); CP_WAIT1(); }
        else             { CP_WAIT0(); }
        __syncthreads();
        const uint32_t* As = dyn + (s & 1) * SSTRIDE;
        const uint32_t* Bs = As + 4224;
        #pragma unroll
        for (int ks = 0; ks < KC; ks += 8) {
            uint32_t af[4][4], bf[4][2];
            #pragma unroll
            for (int i = 0; i < 4; i++) {
                int mb = wm + i * 16;
                af[i][0] = As[(ks + gc    ) * 132 + mb + gr    ];
                af[i][1] = As[(ks + gc    ) * 132 + mb + gr + 8];
                af[i][2] = As[(ks + gc + 4) * 132 + mb + gr    ];
                af[i][3] = As[(ks + gc + 4) * 132 + mb + gr + 8];
            }
            #pragma unroll
            for (int j = 0; j < 4; j++) {
                int nb = wn + j * 8;
                bf[j][0] = Bs[(ks + gc    ) * 132 + nb + gr];
                bf[j][1] = Bs[(ks + gc + 4) * 132 + nb + gr];
            }
            #pragma unroll
            for (int i = 0; i < 4; i++)
                #pragma unroll
                for (int j = 0; j < 4; j++)
                    mma_tf32(acc[i][j], af[i], bf[j]);
        }
        __syncthreads();
    }

    // ---- fused argmin epilogue (reuse smem) ----
    ull* rkey = (ull*)dyn;        // [128] local row keys
    ull* ckey = rkey + 128;       // [128] local col keys
    if (tid < 128) { rkey[tid] = ~0ull; ckey[tid] = ~0ull; }
    __syncthreads();

    const float* a2p = g_a2 + b * HW;
    const float* b2p = g_b2 + b * HW;

    // row candidates: for each of my 8 m-rows, min over my 8 n-cols of (b2[n]-2G)
    #pragma unroll
    for (int i = 0; i < 4; i++) {
        int ml0 = wm + i * 16 + gr, ml1 = ml0 + 8;
        ull r0 = ~0ull, r1 = ~0ull;
        #pragma unroll
        for (int j = 0; j < 4; j++)
            #pragma unroll
            for (int rb = 0; rb < 2; rb++) {
                int n_g = n0 + wn + j * 8 + gc * 2 + rb;
                if (n_g < HW) {
                    float b2v = b2p[n_g];
                    ull k0 = enc_key(b2v - 2.f * acc[i][j][rb],     n_g);
                    ull k1 = enc_key(b2v - 2.f * acc[i][j][2 + rb], n_g);
                    if (k0 < r0) r0 = k0;
                    if (k1 < r1) r1 = k1;
                }
            }
        if (r0 != ~0ull) atomicMin(&rkey[ml0], r0);
        if (r1 != ~0ull) atomicMin(&rkey[ml1], r1);
    }
    // col candidates: for each of my 8 n-cols, min over my 8 m-rows of (a2[m]-2G)
    #pragma unroll
    for (int j = 0; j < 4; j++)
        #pragma unroll
        for (int rb = 0; rb < 2; rb++) {
            int nl = wn + j * 8 + gc * 2 + rb;
            ull cbest = ~0ull;
            #pragma unroll
            for (int i = 0; i < 4; i++) {
                int m0g = m0 + wm + i * 16 + gr;
                if (m0g < HW) {
                    ull k = enc_key(a2p[m0g] - 2.f * acc[i][j][rb], m0g);
                    if (k < cbest) cbest = k;
                }
                if (m0g + 8 < HW) {
                    ull k = enc_key(a2p[m0g + 8] - 2.f * acc[i][j][2 + rb], m0g + 8);
                    if (k < cbest) cbest = k;
                }
            }
            if (cbest != ~0ull) atomicMin(&ckey[nl], cbest);
        }
    __syncthreads();
    if (tid < 128) {
        int m = m0 + tid;
        if (m < HW) atomicMin(&g_key[0][b * HW + m], rkey[tid]);
    } else {
        int n = n0 + tid - 128;
        if (n < HW) atomicMin(&g_key[1][b * HW + n], ckey[tid - 128]);
    }
}

// rank-based top-50 smallest d2 (ties -> lowest index); decodes fused keys
__global__ void k_select() {
    int b = blockIdx.x, dir = blockIdx.y;
    __shared__ float sd[HW];
    __shared__ int   sn[HW];
    int i = threadIdx.x;
    ull key = g_key[dir][b * HW + i];
    const float* own = dir ? g_b2 : g_a2;
    float d2 = own[b * HW + i] + dec_val(key);
    if (d2 < 0.f) d2 = 0.f;
    sd[i] = d2;
    sn[i] = (int)(uint32_t)key;
    __syncthreads();
    float di = sd[i];
    int rank = 0;
    for (int j = 0; j < HW; j++) {
        float dj = sd[j];
        rank += (dj < di) || (dj == di && j < i);
    }
    if (rank < NM) {
        g_sel_in[dir][b * NM + rank] = i;
        g_sel_c [dir][b * NM + rank] = sn[i];
    }
}

__global__ void k_gather(const float* __restrict__ s1, const float* __restrict__ s2) {
    int k = blockIdx.x, b = blockIdx.y, dir = blockIdx.z;
    const float* srcin = dir ? s2 : s1;
    const float* srcc  = dir ? s1 : s2;
    int pin = g_sel_in[dir][b * NM + k];
    int pc  = g_sel_c [dir][b * NM + k];
    float* Xin = g_X[dir * 2 + 0];
    float* Xc  = g_X[dir * 2 + 1];
    int row = b * NM + k;
    float lsum = 0.f;
    for (int c = threadIdx.x; c < C; c += 256) {
        float vi = srcin[((size_t)b * C + c) * HW + pin];
        float vc = srcc [((size_t)b * C + c) * HW + pc];
        Xin[(size_t)row * C + c] = vi;
        Xc [(size_t)row * C + c] = vc;
        float d = vi - vc; lsum += d * d;
    }
    float tot = blockReduceSum(lsum);
    if (threadIdx.x == 0) atomicAdd(&g_acc[1 + dir], (double)tot);
}

__global__ void k_pooled_inv(const float* __restrict__ p1, const float* __restrict__ p2) {
    float lsum = 0.f;
    for (int i = blockIdx.x * blockDim.x + threadIdx.x; i < B * C; i += gridDim.x * blockDim.x) {
        float d = p1[i] - p2[i]; lsum += d * d;
    }
    float tot = blockReduceSum(lsum);
    if (threadIdx.x == 0) atomicAdd(&g_acc[0], (double)tot);
}

__device__ __forceinline__ const float* tensor_ptr(int t, const float* p1, const float* p2) {
    if (t < 4) return g_X[t];
    return (t == 4) ? p1 : p2;
}
__device__ __forceinline__ int tensor_n(int t) { return (t < 4) ? NSEL : B; }

__global__ void k_colsum_part(const float* __restrict__ p1, const float* __restrict__ p2) {
    int t = blockIdx.x, chunk = blockIdx.y, c = threadIdx.x;
    const float* X = tensor_ptr(t, p1, p2);
    int n = tensor_n(t);
    int step = n / 16;
    int n0 = chunk * step, n1 = n0 + step;
    float s = 0.f;
    for (int i = n0; i < n1; i++) s += X[(size_t)i * C + c];
    g_csp[t][chunk][c] = s;
}
__global__ void k_colsum_fin() {
    int t = blockIdx.x, c = threadIdx.x;
    float s = 0.f;
    #pragma unroll
    for (int k = 0; k < 16; k++) s += g_csp[t][k][c];
    g_colsum[t][c] = s;
}

// S = X^T X, upper-triangle 64x64 tiles (78 of 12x12), exact fp32 scalar
__global__ void __launch_bounds__(256) k_gram(const float* __restrict__ p1,
                                              const float* __restrict__ p2) {
    int t = blockIdx.y;
    const float* X = tensor_ptr(t, p1, p2);
    int n = tensor_n(t);
    int idx = blockIdx.x, ti = 0;
    while (idx >= 12 - ti) { idx -= 12 - ti; ti++; }
    int tj = ti + idx;
    int i0 = ti * 64, j0 = tj * 64;

    __shared__ float As[16][64], Bs[16][64];
    int tid = threadIdx.x;
    int tx = tid & 15, ty = tid >> 4;
    int lk = tid >> 4, lo = (tid & 15) * 4;
    float acc[4][4] = {};
    for (int k0 = 0; k0 < n; k0 += 16) {
        *(float4*)&As[lk][lo] = *(const float4*)&X[(size_t)(k0 + lk) * C + i0 + lo];
        *(float4*)&Bs[lk][lo] = *(const float4*)&X[(size_t)(k0 + lk) * C + j0 + lo];
        __syncthreads();
        #pragma unroll
        for (int kk = 0; kk < 16; kk++) {
            float a[4], bb[4];
            *(float4*)a  = *(float4*)&As[kk][ty * 4];
            *(float4*)bb = *(float4*)&Bs[kk][tx * 4];
            #pragma unroll
            for (int i = 0; i < 4; i++)
                #pragma unroll
                for (int j = 0; j < 4; j++) acc[i][j] += a[i] * bb[j];
        }
        __syncthreads();
    }
    float* Sp = g_S[t];
    #pragma unroll
    for (int i = 0; i < 4; i++) {
        int c1 = i0 + ty * 4 + i;
        *(float4*)&Sp[(size_t)c1 * C + j0 + tx * 4] = *(float4*)acc[i];
    }
}

__global__ void k_std() {
    int t = blockIdx.x, c = threadIdx.x;
    float n  = (float)tensor_n(t);
    float mu = g_colsum[t][c] / n;
    float Scc = g_S[t][(size_t)c * C + c];
    float var = (Scc - n * mu * mu) / (n - 1.f);
    float sd  = sqrtf(var + EPSV);
    float contrib = fmaxf(1.f - sd, 0.f);
    float tot = blockReduceSum(contrib);
    if (threadIdx.x == 0) atomicAdd(&g_acc[3 + t], (double)tot);
}

__global__ void k_cov() {
    int t = blockIdx.y;
    float n = (float)tensor_n(t);
    float inv_nm1 = 1.f / (n - 1.f);
    int idx = blockIdx.x, ti = 0;
    while (idx >= 12 - ti) { idx -= 12 - ti; ti++; }
    int tj = ti + idx;
    int i0 = ti * 64, j0 = tj * 64;
    const float* Sp = g_S[t];
    float lsum = 0.f;
    #pragma unroll
    for (int it = 0; it < 16; it++) {
        int e = it * 256 + threadIdx.x;
        int r = e >> 6, cc = e & 63;
        int c1 = i0 + r, c2 = j0 + cc;
        if (c2 > c1) {
            float mu1 = g_colsum[t][c1] / n;
            float mu2 = g_colsum[t][c2] / n;
            float cov = (Sp[(size_t)c1 * C + c2] - n * mu1 * mu2) * inv_nm1;
            lsum += 2.f * cov * cov;
        }
    }
    float tot = blockReduceSum(lsum);
    if (threadIdx.x == 0) atomicAdd(&g_acc[10 + t], (double)tot);
}

__global__ void k_final(float* __restrict__ out) {
    double inv_g = g_acc[0] / (double)(B * C);
    double inv1  = g_acc[1] / (double)((size_t)NSEL * C);
    double inv2  = g_acc[2] / (double)((size_t)NSEL * C);
    double stdt[6], covt[6];
    for (int t = 0; t < 6; t++) {
        stdt[t] = (g_acc[3 + t] / (double)C) * 0.5;
        covt[t] = g_acc[10 + t] / (double)C;
    }
    double glob = 25.0 * inv_g + 25.0 * (stdt[4] + stdt[5]) + (covt[4] + covt[5]);
    double loc  = 0.5 * (25.0 * inv1 + 25.0 * inv2)
                + 0.5 * (25.0 * (stdt[0] + stdt[1]) + 25.0 * (stdt[2] + stdt[3]))
                + 0.5 * ((covt[0] + covt[1]) + (covt[2] + covt[3]));
    out[0] = (float)(0.5 * glob + 0.5 * loc);
}

// ---------------- launch ----------------
extern "C" void kernel_launch(void* const* d_in, const int* in_sizes, int n_in,
                              void* d_out, int out_size) {
    const float* s1 = (const float*)d_in[0];
    const float* p1 = (const float*)d_in[1];
    const float* s2 = (const float*)d_in[2];
    const float* p2 = (const float*)d_in[3];
    float* out = (float*)d_out;

    cudaFuncSetAttribute(k_gemm_fused, cudaFuncAttributeMaxDynamicSharedMemorySize, GSMEM);

    k_init<<<1, 32>>>();
    k_keyinit<<<(2 * B * HW + 255) / 256, 256>>>();
    k_norms<<<dim3(B, 2), HW>>>(s1, s2);
    k_gemm_fused<<<dim3(5, 5, B), 256, GSMEM>>>(s1, s2);
    k_select<<<dim3(B, 2), HW>>>();
    k_gather<<<dim3(NM, B, 2), 256>>>(s1, s2);
    k_pooled_inv<<<48, 256>>>(p1, p2);
    k_colsum_part<<<dim3(6, 16), C>>>(p1, p2);
    k_colsum_fin<<<6, C>>>();
    k_gram<<<dim3(78, 6), 256>>>(p1, p2);
    k_std<<<6, C>>>();
    k_cov<<<dim3(78, 6), 256>>>();
    k_final<<<1, 1>>>(out);
}

// round 6
// speedup vs baseline: 2.9999x; 1.4359x over previous
#include <cuda_runtime.h>
#include <cstdint>
#include <math.h>

#define B    64
#define C    768
#define HW   576
#define NM   50
#define NSEL (B*NM)   // 3200
#define EPSV 1e-5f
#define KC   32
#define NCH  (C/KC)    // 24
#define NCH2 (NSEL/KC) // 100

typedef unsigned long long ull;

// ---------------- scratch ----------------
__device__ float  g_a2[B*HW], g_b2[B*HW];
__device__ ull    g_key[2][B*HW];
__device__ int    g_sel_in[2][NSEL];
__device__ int    g_sel_c [2][NSEL];
__device__ float  g_X[4][(size_t)NSEL*C];
__device__ float  g_S[6][(size_t)C*C];
__device__ float  g_csp[6][16][C];
__device__ float  g_colsum[6][C];
__device__ double g_acc[32];

// ---------------- helpers ----------------
__device__ __forceinline__ void mma_tf32(float c[4], const uint32_t a[4], const uint32_t b[2]) {
    asm volatile(
        "mma.sync.aligned.m16n8k8.row.col.f32.tf32.tf32.f32 "
        "{%0,%1,%2,%3}, {%4,%5,%6,%7}, {%8,%9}, {%0,%1,%2,%3};"
        : "+f"(c[0]), "+f"(c[1]), "+f"(c[2]), "+f"(c[3])
        : "r"(a[0]), "r"(a[1]), "r"(a[2]), "r"(a[3]), "r"(b[0]), "r"(b[1]));
}
#define CP_A16(d, s) asm volatile("cp.async.ca.shared.global [%0], [%1], 16;" :: "r"(d), "l"(s))
#define CP_COMMIT()  asm volatile("cp.async.commit_group;" ::: "memory")
#define CP_WAIT1()   asm volatile("cp.async.wait_group 1;" ::: "memory")
#define CP_WAIT0()   asm volatile("cp.async.wait_group 0;" ::: "memory")

__device__ __forceinline__ uint32_t smem_u32(const void* p) {
    uint32_t a;
    asm("{ .reg .u64 t; cvta.to.shared.u64 t, %1; cvt.u32.u64 %0, t; }" : "=r"(a) : "l"(p));
    return a;
}
__device__ __forceinline__ ull enc_key(float f, int idx) {
    uint32_t u = __float_as_uint(f);
    u = (u & 0x80000000u) ? ~u : (u | 0x80000000u);
    return ((ull)u << 32) | (uint32_t)idx;
}
__device__ __forceinline__ float dec_val(ull k) {
    uint32_t e = (uint32_t)(k >> 32);
    uint32_t u = (e & 0x80000000u) ? (e ^ 0x80000000u) : ~e;
    return __uint_as_float(u);
}

__device__ __forceinline__ float blockReduceSum(float v) {
    __shared__ float sw[32];
    int lane = threadIdx.x & 31, w = threadIdx.x >> 5;
    #pragma unroll
    for (int o = 16; o; o >>= 1) v += __shfl_xor_sync(~0u, v, o);
    if (lane == 0) sw[w] = v;
    __syncthreads();
    int nw = (blockDim.x + 31) >> 5;
    v = (threadIdx.x < nw) ? sw[threadIdx.x] : 0.f;
    if (w == 0) {
        #pragma unroll
        for (int o = 16; o; o >>= 1) v += __shfl_xor_sync(~0u, v, o);
    }
    return v;
}

// ---------------- kernels ----------------
__global__ void k_init() { if (threadIdx.x < 32) g_acc[threadIdx.x] = 0.0; }
__global__ void k_keyinit() {
    int i = blockIdx.x * blockDim.x + threadIdx.x;
    if (i < 2 * B * HW) ((ull*)g_key)[i] = ~0ull;
}

__global__ void k_norms(const float* __restrict__ s1, const float* __restrict__ s2) {
    int b = blockIdx.x, p = threadIdx.x;
    const float* src = blockIdx.y ? s2 : s1;
    float*       dst = blockIdx.y ? g_b2 : g_a2;
    const float* base = src + (size_t)b * C * HW + p;
    float s = 0.f;
    #pragma unroll 8
    for (int c = 0; c < C; c++) { float v = base[(size_t)c * HW]; s += v * v; }
    dst[b * HW + p] = s;
}

// stride 136 words: bank = (8*gc + gr + const) % 32 -> conflict-free fragment LDS
#define LDW     136
#define MATW    (32*LDW)          // 4352 u32 per matrix
#define SSTRIDE (2*MATW)          // 8704 u32 per stage
#define GSMEM   (2 * SSTRIDE * 4) // 69632 B

// ---- fused tf32 GEMM + row/col argmin. CTA 128x128, 8 warps (2m x 4n) ----
__global__ void __launch_bounds__(256, 2) k_gemm_fused(const float* __restrict__ s1,
                                                       const float* __restrict__ s2) {
    extern __shared__ uint32_t dyn[];
    int b  = blockIdx.z;
    int m0 = blockIdx.y * 128, n0 = blockIdx.x * 128;
    int tid = threadIdx.x, w = tid >> 5, lane = tid & 31;
    int wm = (w & 1) * 64, wn = (w >> 1) * 32;
    int gr = lane >> 2, gc = lane & 3;

    const float* Ag = s1 + (size_t)b * C * HW;
    const float* Bg = s2 + (size_t)b * C * HW;
    uint32_t sbase = smem_u32(dyn);

    int rowv[4], colA[4], colB[4];
    #pragma unroll
    for (int t = 0; t < 4; t++) {
        int v = tid + t * 256;
        rowv[t] = v >> 5;
        int col = (v & 31) * 4;
        int ca = m0 + col; if (ca > HW - 4) ca = HW - 4;
        int cb = n0 + col; if (cb > HW - 4) cb = HW - 4;
        colA[t] = ca; colB[t] = cb;
    }
    auto issue_chunk = [&](int s, int stage) {
        int k0 = s * KC;
        uint32_t sA = sbase + stage * (SSTRIDE * 4);
        uint32_t sB = sA + MATW * 4;
        #pragma unroll
        for (int t = 0; t < 4; t++) {
            int v = tid + t * 256;
            uint32_t so = ((v >> 5) * LDW + (v & 31) * 4) * 4;
            CP_A16(sA + so, (const char*)&Ag[(size_t)(k0 + rowv[t]) * HW + colA[t]]);
            CP_A16(sB + so, (const char*)&Bg[(size_t)(k0 + rowv[t]) * HW + colB[t]]);
        }
        CP_COMMIT();
    };

    float acc[4][4][4] = {};
    issue_chunk(0, 0);
    for (int s = 0; s < NCH; s++) {
        if (s + 1 < NCH) { issue_chunk(s + 1, (s + 1) & 1); CP_WAIT1(); }
        else             { CP_WAIT0(); }
        __syncthreads();
        const uint32_t* As = dyn + (s & 1) * SSTRIDE;
        const uint32_t* Bs = As + MATW;
        #pragma unroll
        for (int ks = 0; ks < KC; ks += 8) {
            uint32_t af[4][4], bf[4][2];
            #pragma unroll
            for (int i = 0; i < 4; i++) {
                int mb = wm + i * 16;
                af[i][0] = As[(ks + gc    ) * LDW + mb + gr    ];
                af[i][1] = As[(ks + gc    ) * LDW + mb + gr + 8];
                af[i][2] = As[(ks + gc + 4) * LDW + mb + gr    ];
                af[i][3] = As[(ks + gc + 4) * LDW + mb + gr + 8];
            }
            #pragma unroll
            for (int j = 0; j < 4; j++) {
                int nb = wn + j * 8;
                bf[j][0] = Bs[(ks + gc    ) * LDW + nb + gr];
                bf[j][1] = Bs[(ks + gc + 4) * LDW + nb + gr];
            }
            #pragma unroll
            for (int i = 0; i < 4; i++)
                #pragma unroll
                for (int j = 0; j < 4; j++)
                    mma_tf32(acc[i][j], af[i], bf[j]);
        }
        __syncthreads();
    }

    // ---- fused argmin epilogue ----
    ull* rkey = (ull*)dyn;
    ull* ckey = rkey + 128;
    if (tid < 128) { rkey[tid] = ~0ull; ckey[tid] = ~0ull; }
    __syncthreads();

    const float* a2p = g_a2 + b * HW;
    const float* b2p = g_b2 + b * HW;

    #pragma unroll
    for (int i = 0; i < 4; i++) {
        int ml0 = wm + i * 16 + gr, ml1 = ml0 + 8;
        ull r0 = ~0ull, r1 = ~0ull;
        #pragma unroll
        for (int j = 0; j < 4; j++)
            #pragma unroll
            for (int rb = 0; rb < 2; rb++) {
                int n_g = n0 + wn + j * 8 + gc * 2 + rb;
                if (n_g < HW) {
                    float b2v = b2p[n_g];
                    ull k0 = enc_key(b2v - 2.f * acc[i][j][rb],     n_g);
                    ull k1 = enc_key(b2v - 2.f * acc[i][j][2 + rb], n_g);
                    if (k0 < r0) r0 = k0;
                    if (k1 < r1) r1 = k1;
                }
            }
        if (r0 != ~0ull) atomicMin(&rkey[ml0], r0);
        if (r1 != ~0ull) atomicMin(&rkey[ml1], r1);
    }
    #pragma unroll
    for (int j = 0; j < 4; j++)
        #pragma unroll
        for (int rb = 0; rb < 2; rb++) {
            int nl = wn + j * 8 + gc * 2 + rb;
            ull cbest = ~0ull;
            #pragma unroll
            for (int i = 0; i < 4; i++) {
                int m0g = m0 + wm + i * 16 + gr;
                if (m0g < HW) {
                    ull k = enc_key(a2p[m0g] - 2.f * acc[i][j][rb], m0g);
                    if (k < cbest) cbest = k;
                }
                if (m0g + 8 < HW) {
                    ull k = enc_key(a2p[m0g + 8] - 2.f * acc[i][j][2 + rb], m0g + 8);
                    if (k < cbest) cbest = k;
                }
            }
            if (cbest != ~0ull) atomicMin(&ckey[nl], cbest);
        }
    __syncthreads();
    if (tid < 128) {
        int m = m0 + tid;
        if (m < HW) atomicMin(&g_key[0][b * HW + m], rkey[tid]);
    } else {
        int n = n0 + tid - 128;
        if (n < HW) atomicMin(&g_key[1][b * HW + n], ckey[tid - 128]);
    }
}

// ---- tf32 MMA Gram for the 4 big X tensors: S[t] = X^T X, upper 128x128 tiles ----
__global__ void __launch_bounds__(256, 2) k_gram_mma() {
    extern __shared__ uint32_t dyn[];
    int t = blockIdx.y;
    const float* X = g_X[t];
    int idx = blockIdx.x, ti = 0;
    while (idx >= 6 - ti) { idx -= 6 - ti; ti++; }
    int tj = ti + idx;
    int i0 = ti * 128, j0 = tj * 128;

    int tid = threadIdx.x, w = tid >> 5, lane = tid & 31;
    int wm = (w & 1) * 64, wn = (w >> 1) * 32;
    int gr = lane >> 2, gc = lane & 3;
    uint32_t sbase = smem_u32(dyn);

    auto issue_chunk = [&](int s, int stage) {
        int k0 = s * KC;
        uint32_t sA = sbase + stage * (SSTRIDE * 4);
        uint32_t sB = sA + MATW * 4;
        #pragma unroll
        for (int tt = 0; tt < 4; tt++) {
            int v = tid + tt * 256;
            int row = v >> 5, col = (v & 31) * 4;
            uint32_t so = (row * LDW + col) * 4;
            CP_A16(sA + so, (const char*)&X[(size_t)(k0 + row) * C + i0 + col]);
            CP_A16(sB + so, (const char*)&X[(size_t)(k0 + row) * C + j0 + col]);
        }
        CP_COMMIT();
    };

    float acc[4][4][4] = {};
    issue_chunk(0, 0);
    for (int s = 0; s < NCH2; s++) {
        if (s + 1 < NCH2) { issue_chunk(s + 1, (s + 1) & 1); CP_WAIT1(); }
        else              { CP_WAIT0(); }
        __syncthreads();
        const uint32_t* As = dyn + (s & 1) * SSTRIDE;
        const uint32_t* Bs = As + MATW;
        #pragma unroll
        for (int ks = 0; ks < KC; ks += 8) {
            uint32_t af[4][4], bf[4][2];
            #pragma unroll
            for (int i = 0; i < 4; i++) {
                int mb = wm + i * 16;
                af[i][0] = As[(ks + gc    ) * LDW + mb + gr    ];
                af[i][1] = As[(ks + gc    ) * LDW + mb + gr + 8];
                af[i][2] = As[(ks + gc + 4) * LDW + mb + gr    ];
                af[i][3] = As[(ks + gc + 4) * LDW + mb + gr + 8];
            }
            #pragma unroll
            for (int j = 0; j < 4; j++) {
                int nb = wn + j * 8;
                bf[j][0] = Bs[(ks + gc    ) * LDW + nb + gr];
                bf[j][1] = Bs[(ks + gc + 4) * LDW + nb + gr];
            }
            #pragma unroll
            for (int i = 0; i < 4; i++)
                #pragma unroll
                for (int j = 0; j < 4; j++)
                    mma_tf32(acc[i][j], af[i], bf[j]);
        }
        __syncthreads();
    }

    float* Sp = g_S[t];
    #pragma unroll
    for (int i = 0; i < 4; i++) {
        int c1a = i0 + wm + i * 16 + gr;
        #pragma unroll
        for (int j = 0; j < 4; j++) {
            int c2 = j0 + wn + j * 8 + gc * 2;
            *(float2*)&Sp[(size_t)c1a * C + c2]       = make_float2(acc[i][j][0], acc[i][j][1]);
            *(float2*)&Sp[(size_t)(c1a + 8) * C + c2] = make_float2(acc[i][j][2], acc[i][j][3]);
        }
    }
}

// rank-based top-50 smallest d2 (ties -> lowest index)
__global__ void k_select() {
    int b = blockIdx.x, dir = blockIdx.y;
    __shared__ float sd[HW];
    __shared__ int   sn[HW];
    int i = threadIdx.x;
    ull key = g_key[dir][b * HW + i];
    const float* own = dir ? g_b2 : g_a2;
    float d2 = own[b * HW + i] + dec_val(key);
    if (d2 < 0.f) d2 = 0.f;
    sd[i] = d2;
    sn[i] = (int)(uint32_t)key;
    __syncthreads();
    float di = sd[i];
    int rank = 0;
    for (int j = 0; j < HW; j++) {
        float dj = sd[j];
        rank += (dj < di) || (dj == di && j < i);
    }
    if (rank < NM) {
        g_sel_in[dir][b * NM + rank] = i;
        g_sel_c [dir][b * NM + rank] = sn[i];
    }
}

__global__ void k_gather(const float* __restrict__ s1, const float* __restrict__ s2) {
    int k = blockIdx.x, b = blockIdx.y, dir = blockIdx.z;
    const float* srcin = dir ? s2 : s1;
    const float* srcc  = dir ? s1 : s2;
    int pin = g_sel_in[dir][b * NM + k];
    int pc  = g_sel_c [dir][b * NM + k];
    float* Xin = g_X[dir * 2 + 0];
    float* Xc  = g_X[dir * 2 + 1];
    int row = b * NM + k;
    float lsum = 0.f;
    for (int c = threadIdx.x; c < C; c += 256) {
        float vi = srcin[((size_t)b * C + c) * HW + pin];
        float vc = srcc [((size_t)b * C + c) * HW + pc];
        Xin[(size_t)row * C + c] = vi;
        Xc [(size_t)row * C + c] = vc;
        float d = vi - vc; lsum += d * d;
    }
    float tot = blockReduceSum(lsum);
    if (threadIdx.x == 0) atomicAdd(&g_acc[1 + dir], (double)tot);
}

__global__ void k_pooled_inv(const float* __restrict__ p1, const float* __restrict__ p2) {
    float lsum = 0.f;
    for (int i = blockIdx.x * blockDim.x + threadIdx.x; i < B * C; i += gridDim.x * blockDim.x) {
        float d = p1[i] - p2[i]; lsum += d * d;
    }
    float tot = blockReduceSum(lsum);
    if (threadIdx.x == 0) atomicAdd(&g_acc[0], (double)tot);
}

__device__ __forceinline__ const float* tensor_ptr(int t, const float* p1, const float* p2) {
    if (t < 4) return g_X[t];
    return (t == 4) ? p1 : p2;
}
__device__ __forceinline__ int tensor_n(int t) { return (t < 4) ? NSEL : B; }

__global__ void k_colsum_part(const float* __restrict__ p1, const float* __restrict__ p2) {
    int t = blockIdx.x, chunk = blockIdx.y, c = threadIdx.x;
    const float* X = tensor_ptr(t, p1, p2);
    int n = tensor_n(t);
    int step = n / 16;
    int n0 = chunk * step, n1 = n0 + step;
    float s = 0.f;
    for (int i = n0; i < n1; i++) s += X[(size_t)i * C + c];
    g_csp[t][chunk][c] = s;
}
__global__ void k_colsum_fin() {
    int t = blockIdx.x, c = threadIdx.x;
    float s = 0.f;
    #pragma unroll
    for (int k = 0; k < 16; k++) s += g_csp[t][k][c];
    g_colsum[t][c] = s;
}

// exact fp32 Gram for the 2 pooled tensors (n=64), upper 64x64 tiles
__global__ void __launch_bounds__(256) k_gram(const float* __restrict__ p1,
                                              const float* __restrict__ p2) {
    int t = 4 + blockIdx.y;
    const float* X = tensor_ptr(t, p1, p2);
    int n = tensor_n(t);
    int idx = blockIdx.x, ti = 0;
    while (idx >= 12 - ti) { idx -= 12 - ti; ti++; }
    int tj = ti + idx;
    int i0 = ti * 64, j0 = tj * 64;

    __shared__ float As[16][64], Bs[16][64];
    int tid = threadIdx.x;
    int tx = tid & 15, ty = tid >> 4;
    int lk = tid >> 4, lo = (tid & 15) * 4;
    float acc[4][4] = {};
    for (int k0 = 0; k0 < n; k0 += 16) {
        *(float4*)&As[lk][lo] = *(const float4*)&X[(size_t)(k0 + lk) * C + i0 + lo];
        *(float4*)&Bs[lk][lo] = *(const float4*)&X[(size_t)(k0 + lk) * C + j0 + lo];
        __syncthreads();
        #pragma unroll
        for (int kk = 0; kk < 16; kk++) {
            float a[4], bb[4];
            *(float4*)a  = *(float4*)&As[kk][ty * 4];
            *(float4*)bb = *(float4*)&Bs[kk][tx * 4];
            #pragma unroll
            for (int i = 0; i < 4; i++)
                #pragma unroll
                for (int j = 0; j < 4; j++) acc[i][j] += a[i] * bb[j];
        }
        __syncthreads();
    }
    float* Sp = g_S[t];
    #pragma unroll
    for (int i = 0; i < 4; i++) {
        int c1 = i0 + ty * 4 + i;
        *(float4*)&Sp[(size_t)c1 * C + j0 + tx * 4] = *(float4*)acc[i];
    }
}

__global__ void k_std() {
    int t = blockIdx.x, c = threadIdx.x;
    float n  = (float)tensor_n(t);
    float mu = g_colsum[t][c] / n;
    float Scc = g_S[t][(size_t)c * C + c];
    float var = (Scc - n * mu * mu) / (n - 1.f);
    float sd  = sqrtf(var + EPSV);
    float contrib = fmaxf(1.f - sd, 0.f);
    float tot = blockReduceSum(contrib);
    if (threadIdx.x == 0) atomicAdd(&g_acc[3 + t], (double)tot);
}

__global__ void k_cov() {
    int t = blockIdx.y;
    float n = (float)tensor_n(t);
    float inv_nm1 = 1.f / (n - 1.f);
    int idx = blockIdx.x, ti = 0;
    while (idx >= 12 - ti) { idx -= 12 - ti; ti++; }
    int tj = ti + idx;
    int i0 = ti * 64, j0 = tj * 64;
    const float* Sp = g_S[t];
    float lsum = 0.f;
    #pragma unroll
    for (int it = 0; it < 16; it++) {
        int e = it * 256 + threadIdx.x;
        int r = e >> 6, cc = e & 63;
        int c1 = i0 + r, c2 = j0 + cc;
        if (c2 > c1) {
            float mu1 = g_colsum[t][c1] / n;
            float mu2 = g_colsum[t][c2] / n;
            float cov = (Sp[(size_t)c1 * C + c2] - n * mu1 * mu2) * inv_nm1;
            lsum += 2.f * cov * cov;
        }
    }
    float tot = blockReduceSum(lsum);
    if (threadIdx.x == 0) atomicAdd(&g_acc[10 + t], (double)tot);
}

__global__ void k_final(float* __restrict__ out) {
    double inv_g = g_acc[0] / (double)(B * C);
    double inv1  = g_acc[1] / (double)((size_t)NSEL * C);
    double inv2  = g_acc[2] / (double)((size_t)NSEL * C);
    double stdt[6], covt[6];
    for (int t = 0; t < 6; t++) {
        stdt[t] = (g_acc[3 + t] / (double)C) * 0.5;
        covt[t] = g_acc[10 + t] / (double)C;
    }
    double glob = 25.0 * inv_g + 25.0 * (stdt[4] + stdt[5]) + (covt[4] + covt[5]);
    double loc  = 0.5 * (25.0 * inv1 + 25.0 * inv2)
                + 0.5 * (25.0 * (stdt[0] + stdt[1]) + 25.0 * (stdt[2] + stdt[3]))
                + 0.5 * ((covt[0] + covt[1]) + (covt[2] + covt[3]));
    out[0] = (float)(0.5 * glob + 0.5 * loc);
}

// ---------------- launch ----------------
extern "C" void kernel_launch(void* const* d_in, const int* in_sizes, int n_in,
                              void* d_out, int out_size) {
    const float* s1 = (const float*)d_in[0];
    const float* p1 = (const float*)d_in[1];
    const float* s2 = (const float*)d_in[2];
    const float* p2 = (const float*)d_in[3];
    float* out = (float*)d_out;

    cudaFuncSetAttribute(k_gemm_fused, cudaFuncAttributeMaxDynamicSharedMemorySize, GSMEM);
    cudaFuncSetAttribute(k_gram_mma,   cudaFuncAttributeMaxDynamicSharedMemorySize, GSMEM);

    k_init<<<1, 32>>>();
    k_keyinit<<<(2 * B * HW + 255) / 256, 256>>>();
    k_norms<<<dim3(B, 2), HW>>>(s1, s2);
    k_gemm_fused<<<dim3(5, 5, B), 256, GSMEM>>>(s1, s2);
    k_select<<<dim3(B, 2), HW>>>();
    k_gather<<<dim3(NM, B, 2), 256>>>(s1, s2);
    k_pooled_inv<<<48, 256>>>(p1, p2);
    k_colsum_part<<<dim3(6, 16), C>>>(p1, p2);
    k_colsum_fin<<<6, C>>>();
    k_gram_mma<<<dim3(21, 4), 256, GSMEM>>>();
    k_gram<<<dim3(78, 2), 256>>>(p1, p2);
    k_std<<<6, C>>>();
    k_cov<<<dim3(78, 6), 256>>>();
    k_final<<<1, 1>>>(out);
}